// round 12
// baseline (speedup 1.0000x reference)
#include <cuda_runtime.h>
#include <cuda_fp16.h>
#include <math.h>
#include <stdint.h>

#define NS       131072
#define DIMS     16
#define DIMSC    16
#define UNITS    512
#define BINS     10
#define DT       8
#define FEAT_IN  24
#define FEAT_OUT 248
#define NBLOCKS  8
#define MIN_W    0.001f
#define MIN_H    0.001f
#define MIN_D    0.001f

#define MTS      64
#define NTHREADS 512

#define PADH     520
#define PADW     520
#define PADW2    264

// g_img per-flow-block layout (bytes) — unchanged:
//  L0: 2 chunks x 33280   (chunk = 16 k-rows: hi 16640 + lo 16640)
//  L1: 32 chunks x 33280
//  L2: 16 chunks x 33792  (chunk = 32 k-rows: hi 16896 + lo 16896)
#define L0_OFF   0
#define L1_OFF   66560
#define L2_OFF   1131520
#define BLK_BYTES 1672192

// smem byte offsets
#define OFF_AH   0         // activation [64 x 520] fp16 = 66560 (also fp32 park 64x260)
#define OFF_W    66560     // 4 weight slots x 33792 = 135168
#define WSLOT    33792
#define OFF_IH   201728    // input tile hi [64 x 40] fp16
#define OFF_IL   206848    // input tile lo
#define SMEM_TOTAL 211968

__device__ float g_z[NS * DIMS];
__device__ __align__(16) uint8_t g_img[(size_t)NBLOCKS * BLK_BYTES];

__device__ __forceinline__ uint32_t smem_u32(const void* p) {
    return (uint32_t)__cvta_generic_to_shared(p);
}
#define CP16(s, g)  asm volatile("cp.async.cg.shared.global [%0], [%1], 16;" :: "r"(s), "l"(g))
#define CPCOMMIT()  asm volatile("cp.async.commit_group;")
#define CPWAIT1()   asm volatile("cp.async.wait_group 1;" ::: "memory")
#define CPWAIT0()   asm volatile("cp.async.wait_group 0;" ::: "memory")

__device__ __forceinline__ void ldm4(uint32_t* r, uint32_t a) {
    asm volatile("ldmatrix.sync.aligned.m8n8.x4.shared.b16 {%0,%1,%2,%3}, [%4];"
        : "=r"(r[0]), "=r"(r[1]), "=r"(r[2]), "=r"(r[3]) : "r"(a));
}
__device__ __forceinline__ void ldm4t(uint32_t* r, uint32_t a) {
    asm volatile("ldmatrix.sync.aligned.m8n8.x4.trans.shared.b16 {%0,%1,%2,%3}, [%4];"
        : "=r"(r[0]), "=r"(r[1]), "=r"(r[2]), "=r"(r[3]) : "r"(a));
}
__device__ __forceinline__ void mma16816(float* d, const uint32_t* a, uint32_t b0, uint32_t b1) {
    asm volatile("mma.sync.aligned.m16n8k16.row.col.f32.f16.f16.f32 "
        "{%0,%1,%2,%3}, {%4,%5,%6,%7}, {%8,%9}, {%0,%1,%2,%3};"
        : "+f"(d[0]), "+f"(d[1]), "+f"(d[2]), "+f"(d[3])
        : "r"(a[0]), "r"(a[1]), "r"(a[2]), "r"(a[3]), "r"(b0), "r"(b1));
}
__device__ __forceinline__ int insert_bit(int f, int p, int bit) {
    int lo = f & ((1 << p) - 1);
    int hi = f >> p;
    return (hi << (p + 1)) | (bit << p) | lo;
}

// ---------------- init ----------------
__global__ void init_kernel(const float* __restrict__ x, float* __restrict__ out) {
    int i = blockIdx.x * blockDim.x + threadIdx.x;
    if (i < NS * DIMS) g_z[i] = x[i];
    if (i < NS) out[i] = 0.f;
}

// ---------------- weight image prep (unchanged) ----------------
__global__ void prep_kernel(const float* __restrict__ W0,
                            const float* __restrict__ W1,
                            const float* __restrict__ W2) {
    int plane = blockIdx.x;
    int b = plane / 100, r = plane % 100;
    uint8_t* gb = g_img + (size_t)b * BLK_BYTES;
    int layer, chunk, half;
    if (r < 4)       { layer = 0; chunk = r >> 1;        half = r & 1; }
    else if (r < 68) { int q = r - 4;  layer = 1; chunk = q >> 1; half = q & 1; }
    else             { int q = r - 68; layer = 2; chunk = q >> 1; half = q & 1; }

    int rows  = (layer == 2) ? 32 : 16;
    int padc  = (layer == 2) ? PADW2 : PADW;
    int ncols = (layer == 2) ? FEAT_OUT : UNITS;
    uint8_t* dst;
    if (layer == 0)      dst = gb + L0_OFF + chunk * 33280 + half * 16640;
    else if (layer == 1) dst = gb + L1_OFF + chunk * 33280 + half * 16640;
    else                 dst = gb + L2_OFF + chunk * 33792 + half * 16896;
    __half* d16 = (__half*)dst;

    for (int i = threadIdx.x; i < rows * padc; i += blockDim.x) {
        int row = i / padc, col = i % padc;
        int k = chunk * rows + row;
        float w = 0.f;
        if (col < ncols) {
            if (layer == 0)      { if (k < FEAT_IN) w = W0[((size_t)b * FEAT_IN + k) * UNITS + col]; }
            else if (layer == 1) { w = W1[((size_t)b * UNITS + k) * UNITS + col]; }
            else                 { w = W2[((size_t)b * UNITS + k) * FEAT_OUT + col]; }
        }
        __half hi = __float2half(w);
        float v = half ? (w - __half2float(hi)) : w;
        d16[i] = __float2half(v);
    }
}

// ---------------- helpers ----------------
__device__ __forceinline__ void copy16(uint32_t sdst, const uint8_t* g, int n16, int tid) {
    for (int i = tid; i < n16; i += NTHREADS)
        CP16(sdst + i * 16, g + (size_t)i * 16);
}

// epilogue L0/L1: bias+relu -> fp16 activation tile.  warp = m64 x n32
// acc layout: acc[mh*16 + np*8 + j*4 + rr*2 + e]
__device__ __forceinline__ void epi_h(float* acc, const float* __restrict__ bias,
                                      uint8_t* sm, int nw, int lane) {
    int rq = lane >> 2;
    int c0 = (lane & 3) * 2;
    uint8_t* AH = sm + OFF_AH;
    #pragma unroll
    for (int np = 0; np < 2; np++) {
        #pragma unroll
        for (int j = 0; j < 2; j++) {
            int col = nw * 32 + np * 16 + j * 8 + c0;
            float bx = bias[col], by = bias[col + 1];
            #pragma unroll
            for (int mh = 0; mh < 4; mh++) {
                float* a = acc + mh * 16 + np * 8 + j * 4;
                #pragma unroll
                for (int rr = 0; rr < 2; rr++) {
                    float vx = fmaxf(a[rr * 2 + 0] + bx, 0.f);
                    float vy = fmaxf(a[rr * 2 + 1] + by, 0.f);
                    int row = mh * 16 + rr * 8 + rq;
                    uint32_t off = (uint32_t)(row * PADH + col) * 2;
                    *(__half2*)(AH + off) = __halves2half2(__float2half(vx), __float2half(vy));
                }
            }
        }
    }
}

// ---------------- main fused flow-block kernel ----------------
__global__ void __launch_bounds__(NTHREADS, 1)
flow_block_kernel(int blk,
                  const float* __restrict__ cc,
                  const float* __restrict__ B0, const float* __restrict__ B1,
                  const float* __restrict__ B2,
                  float* __restrict__ out)
{
    extern __shared__ __align__(128) uint8_t sm[];
    const uint32_t s0 = smem_u32(sm);
    const int tid  = threadIdx.x;
    const int wid  = tid >> 5;
    const int lane = tid & 31;
    const int nw   = wid;          // L0/L1: 16 column groups x n32
    const int mw2  = wid & 1;      // L2: 2 sample groups x m32
    const int nw2  = wid >> 1;     // L2: 8 column groups x n32
    const int row0 = blockIdx.x * MTS;
    const int p    = blk >> 1;
    const int cbit = 1 - (blk & 1);
    const uint8_t* gb = g_img + (size_t)blk * BLK_BYTES;

    const int l15  = lane & 15;
    const int lhi  = lane >> 4;
    uint32_t aoffM[4], ioffM[4];
    #pragma unroll
    for (int mh = 0; mh < 4; mh++) {
        aoffM[mh] = (uint32_t)((mh * 16 + l15) * (PADH * 2)) + lhi * 16;
        ioffM[mh] = (uint32_t)((mh * 16 + l15) * 80) + lhi * 16;
    }
    const int ar2  = mw2 * 32 + l15;
    const uint32_t aoff2_0 = (uint32_t)(ar2 * (PADH * 2)) + lhi * 16;
    const uint32_t aoff2_1 = aoff2_0 + 16 * (PADH * 2);

    const int krow = (lane & 7) + ((lane >> 3) & 1) * 8;
    const uint32_t woff1 = (uint32_t)(krow * (PADW * 2))  + (uint32_t)lhi * 16;
    const uint32_t woff2 = (uint32_t)(krow * (PADW2 * 2)) + (uint32_t)lhi * 16;

    // ---- stage L0 weights: chunk0 -> slot0, chunk1 -> slot1 ----
    copy16(s0 + OFF_W + 0 * WSLOT, gb + L0_OFF,         2080, tid);
    CPCOMMIT();
    copy16(s0 + OFF_W + 1 * WSLOT, gb + L0_OFF + 33280, 2080, tid);
    CPCOMMIT();

    // ---- build input tile [64 x 32] fp16 hi/lo, zero-padded ----
    for (int i = tid; i < 1280; i += NTHREADS) {
        ((uint32_t*)(sm + OFF_IH))[i] = 0u;
        ((uint32_t*)(sm + OFF_IL))[i] = 0u;
    }
    __syncthreads();
    for (int i = tid; i < MTS * FEAT_IN; i += NTHREADS) {
        int m = i / FEAT_IN, f = i % FEAT_IN;
        float v = (f < DT) ? g_z[(row0 + m) * DIMS + insert_bit(f, p, cbit)]
                           : cc[(row0 + m) * DIMSC + (f - DT)];
        __half hi = __float2half(v);
        ((__half*)(sm + OFF_IH))[m * 40 + f] = hi;
        ((__half*)(sm + OFF_IL))[m * 40 + f] = __float2half(v - __half2float(hi));
    }
    CPWAIT0();
    __syncthreads();

    // ---- issue L1 chunk0 -> slot2, chunk1 -> slot3 (overlap with L0 compute) ----
    copy16(s0 + OFF_W + 2 * WSLOT, gb + L1_OFF,         2080, tid);
    CPCOMMIT();
    copy16(s0 + OFF_W + 3 * WSLOT, gb + L1_OFF + 33280, 2080, tid);
    CPCOMMIT();

    float acc[64];
    #pragma unroll
    for (int i = 0; i < 64; i++) acc[i] = 0.f;

    // ---- L0: 2 k16-steps, 3-pass (ah*bh, ah*bl, al*bh), warp = m64 x n32 ----
    #pragma unroll
    for (int ks = 0; ks < 2; ks++) {
        uint32_t ah[4][4], al[4][4];
        #pragma unroll
        for (int mh = 0; mh < 4; mh++) {
            ldm4(ah[mh], s0 + OFF_IH + ioffM[mh] + ks * 32);
            ldm4(al[mh], s0 + OFF_IL + ioffM[mh] + ks * 32);
        }
        uint32_t wb = s0 + OFF_W + ks * WSLOT;
        #pragma unroll
        for (int np = 0; np < 2; np++) {
            uint32_t bh[4], bl[4];
            uint32_t ba = wb + woff1 + (uint32_t)(nw * 32 + np * 16) * 2;
            ldm4t(bh, ba);
            ldm4t(bl, ba + 16640);
            #pragma unroll
            for (int mh = 0; mh < 4; mh++) {
                float* d0 = acc + mh * 16 + np * 8;
                mma16816(d0,     ah[mh], bh[0], bh[1]);
                mma16816(d0 + 4, ah[mh], bh[2], bh[3]);
            }
            #pragma unroll
            for (int mh = 0; mh < 4; mh++) {
                float* d0 = acc + mh * 16 + np * 8;
                mma16816(d0,     ah[mh], bl[0], bl[1]);
                mma16816(d0 + 4, ah[mh], bl[2], bl[3]);
            }
            #pragma unroll
            for (int mh = 0; mh < 4; mh++) {
                float* d0 = acc + mh * 16 + np * 8;
                mma16816(d0,     al[mh], bh[0], bh[1]);
                mma16816(d0 + 4, al[mh], bh[2], bh[3]);
            }
        }
    }
    __syncthreads();   // L0 slot reads retired (slots 0,1 free)

    // ---- epilogue0 (L1 chunk0/1 copies still in flight) ----
    epi_h(acc, B0, sm, nw, lane);
    #pragma unroll
    for (int i = 0; i < 64; i++) acc[i] = 0.f;

    // ---- L1: 32 k16-chunks, depth-2 prefetch; chunk c lives in slot (c+2)&3 ----
    for (int c = 0; c < 32; c++) {
        if (c < 31) { CPWAIT1(); } else { CPWAIT0(); }
        __syncthreads();
        if (c + 2 < 32) {
            copy16(s0 + OFF_W + (uint32_t)(c & 3) * WSLOT,
                   gb + L1_OFF + (size_t)(c + 2) * 33280, 2080, tid);
            CPCOMMIT();
        }
        uint32_t buf = s0 + OFF_W + (uint32_t)((c + 2) & 3) * WSLOT;
        uint32_t ah[4][4];
        uint32_t ao = (uint32_t)(c * 32);
        #pragma unroll
        for (int mh = 0; mh < 4; mh++)
            ldm4(ah[mh], s0 + OFF_AH + aoffM[mh] + ao);
        #pragma unroll
        for (int np = 0; np < 2; np++) {
            uint32_t bh[4], bl[4];
            uint32_t ba = buf + woff1 + (uint32_t)(nw * 32 + np * 16) * 2;
            ldm4t(bh, ba);
            ldm4t(bl, ba + 16640);
            #pragma unroll
            for (int mh = 0; mh < 4; mh++) {
                float* d0 = acc + mh * 16 + np * 8;
                mma16816(d0,     ah[mh], bh[0], bh[1]);
                mma16816(d0 + 4, ah[mh], bh[2], bh[3]);
            }
            #pragma unroll
            for (int mh = 0; mh < 4; mh++) {
                float* d0 = acc + mh * 16 + np * 8;
                mma16816(d0,     ah[mh], bl[0], bl[1]);
                mma16816(d0 + 4, ah[mh], bl[2], bl[3]);
            }
        }
    }
    __syncthreads();   // L1 compute retired (act reads done, all slots free)

    // ---- issue L2 chunk0 -> slot2, chunk1 -> slot3; epilogue1 overlapped ----
    copy16(s0 + OFF_W + 2 * WSLOT, gb + L2_OFF,         2112, tid);
    CPCOMMIT();
    copy16(s0 + OFF_W + 3 * WSLOT, gb + L2_OFF + 33792, 2112, tid);
    CPCOMMIT();
    epi_h(acc, B1, sm, nw, lane);

    float acc2[32];
    #pragma unroll
    for (int i = 0; i < 32; i++) acc2[i] = 0.f;

    // ---- L2: 16 k32-chunks, depth-2 prefetch, warp = m32 x n32 ----
    for (int c = 0; c < 16; c++) {
        if (c < 15) { CPWAIT1(); } else { CPWAIT0(); }
        __syncthreads();
        if (c + 2 < 16) {
            copy16(s0 + OFF_W + (uint32_t)(c & 3) * WSLOT,
                   gb + L2_OFF + (size_t)(c + 2) * 33792, 2112, tid);
            CPCOMMIT();
        }
        uint32_t wbs = s0 + OFF_W + (uint32_t)((c + 2) & 3) * WSLOT;
        #pragma unroll
        for (int ks = 0; ks < 2; ks++) {
            uint32_t ah0[4], ah1[4];
            uint32_t ao = (uint32_t)(c * 64 + ks * 32);
            ldm4(ah0, s0 + OFF_AH + aoff2_0 + ao);
            ldm4(ah1, s0 + OFF_AH + aoff2_1 + ao);
            #pragma unroll
            for (int np = 0; np < 2; np++) {
                uint32_t bh[4], bl[4];
                uint32_t ba = wbs + (uint32_t)(ks * 16 * PADW2 * 2) + woff2
                            + (uint32_t)(nw2 * 32 + np * 16) * 2;
                ldm4t(bh, ba);
                ldm4t(bl, ba + 16896);
                float* d00 = acc2 + np * 16;
                float* d01 = acc2 + np * 16 + 4;
                float* d10 = acc2 + np * 16 + 8;
                float* d11 = acc2 + np * 16 + 12;
                mma16816(d00, ah0, bh[0], bh[1]);
                mma16816(d10, ah1, bh[0], bh[1]);
                mma16816(d01, ah0, bh[2], bh[3]);
                mma16816(d11, ah1, bh[2], bh[3]);
                mma16816(d00, ah0, bl[0], bl[1]);
                mma16816(d10, ah1, bl[0], bl[1]);
                mma16816(d01, ah0, bl[2], bl[3]);
                mma16816(d11, ah1, bl[2], bl[3]);
            }
        }
    }
    __syncthreads();   // L2 act reads retired

    // ---- park params fp32 into AH region (h dead) ----
    float* park = (float*)(sm + OFF_AH);
    {
        int rb = mw2 * 32 + (lane >> 2);
        int c0 = (lane & 3) * 2;
        #pragma unroll
        for (int np = 0; np < 2; np++) {
            #pragma unroll
            for (int j = 0; j < 2; j++) {
                int col = nw2 * 32 + np * 16 + j * 8 + c0;
                #pragma unroll
                for (int mh = 0; mh < 2; mh++) {
                    float* a = acc2 + np * 16 + mh * 8 + j * 4;
                    #pragma unroll
                    for (int rr = 0; rr < 2; rr++) {
                        int row = rb + mh * 16 + rr * 8;
                        *(float2*)(park + row * 260 + col) = make_float2(a[rr * 2 + 0], a[rr * 2 + 1]);
                    }
                }
            }
        }
    }
    __syncthreads();

    // ---- spline + logdet ----
    {
        const int m2 = tid >> 3;
        const int dg = tid & 7;
        float pr[31];
        #pragma unroll
        for (int j = 0; j < 31; j++)
            pr[j] = park[m2 * 260 + dg * 31 + j] + B2[dg * 31 + j];

        const int tdim = insert_bit(dg, p, 1 - cbit);
        const float xv = g_z[(row0 + m2) * DIMS + tdim];

        float ww[BINS], hh[BINS], dd[BINS + 1];
        float mx = pr[0];
        #pragma unroll
        for (int i = 1; i < BINS; i++) mx = fmaxf(mx, pr[i]);
        float ssum = 0.f;
        #pragma unroll
        for (int i = 0; i < BINS; i++) { ww[i] = expf(pr[i] - mx); ssum += ww[i]; }
        float sc = (1.0f - MIN_W * (float)BINS) / ssum;
        #pragma unroll
        for (int i = 0; i < BINS; i++) ww[i] = MIN_W + ww[i] * sc;

        mx = pr[BINS];
        #pragma unroll
        for (int i = 1; i < BINS; i++) mx = fmaxf(mx, pr[BINS + i]);
        ssum = 0.f;
        #pragma unroll
        for (int i = 0; i < BINS; i++) { hh[i] = expf(pr[BINS + i] - mx); ssum += hh[i]; }
        sc = (1.0f - MIN_H * (float)BINS) / ssum;
        #pragma unroll
        for (int i = 0; i < BINS; i++) hh[i] = MIN_H + hh[i] * sc;

        #pragma unroll
        for (int i = 0; i <= BINS; i++) {
            float u = pr[2 * BINS + i];
            dd[i] = MIN_D + (fmaxf(u, 0.f) + log1pf(expf(-fabsf(u))));
        }

        float cw[BINS + 1], ch[BINS + 1];
        cw[0] = 0.f; ch[0] = 0.f;
        #pragma unroll
        for (int i = 1; i <= BINS; i++) { cw[i] = cw[i-1] + ww[i-1]; ch[i] = ch[i-1] + hh[i-1]; }

        int cnt = 0;
        #pragma unroll
        for (int i = 0; i <= BINS; i++) cnt += (xv >= cw[i]) ? 1 : 0;
        int idx = cnt - 1;
        idx = idx < 0 ? 0 : (idx > BINS - 1 ? BINS - 1 : idx);

        float xk = 0.f, wk = 1.f, yk = 0.f, hk = 1.f, dk = 1.f, dk1 = 1.f;
        #pragma unroll
        for (int i = 0; i < BINS; i++)
            if (i == idx) { xk = cw[i]; wk = ww[i]; yk = ch[i]; hk = hh[i]; dk = dd[i]; dk1 = dd[i+1]; }

        float th  = fminf(fmaxf((xv - xk) / wk, 0.f), 1.f);
        float sr  = hk / wk;
        float t1  = th * (1.f - th);
        float den = sr + (dk1 + dk - 2.f * sr) * t1;
        float y   = yk + hk * (sr * th * th + dk * t1) / den;
        float omt = 1.f - th;
        float ld  = 2.f * logf(sr)
                  + logf(dk1 * th * th + 2.f * sr * t1 + dk * omt * omt)
                  - 2.f * logf(den);

        g_z[(row0 + m2) * DIMS + tdim] = y;

        #pragma unroll
        for (int off = 4; off > 0; off >>= 1)
            ld += __shfl_down_sync(0xffffffffu, ld, off);
        if (dg == 0) out[row0 + m2] += ld;
    }
}

extern "C" void kernel_launch(void* const* d_in, const int* in_sizes, int n_in,
                              void* d_out, int out_size) {
    const float* x  = (const float*)d_in[0];
    const float* c  = (const float*)d_in[1];
    const float* W0 = (const float*)d_in[2];
    const float* b0 = (const float*)d_in[3];
    const float* W1 = (const float*)d_in[4];
    const float* b1 = (const float*)d_in[5];
    const float* W2 = (const float*)d_in[6];
    const float* b2 = (const float*)d_in[7];
    float* out = (float*)d_out;

    cudaFuncSetAttribute(flow_block_kernel,
                         cudaFuncAttributeMaxDynamicSharedMemorySize, SMEM_TOTAL);

    init_kernel<<<(NS * DIMS + 255) / 256, 256>>>(x, out);
    prep_kernel<<<NBLOCKS * 100, 256>>>(W0, W1, W2);

    for (int b = 0; b < NBLOCKS; b++) {
        flow_block_kernel<<<NS / MTS, NTHREADS, SMEM_TOTAL>>>(
            b, c,
            b0 + (size_t)b * UNITS,
            b1 + (size_t)b * UNITS,
            b2 + (size_t)b * FEAT_OUT,
            out);
    }
}

// round 13
// speedup vs baseline: 1.1502x; 1.1502x over previous
#include <cuda_runtime.h>
#include <cuda_fp16.h>
#include <math.h>
#include <stdint.h>

#define NS       131072
#define DIMS     16
#define DIMSC    16
#define UNITS    512
#define BINS     10
#define DT       8
#define FEAT_IN  24
#define FEAT_OUT 248
#define NBLOCKS  8
#define MIN_W    0.001f
#define MIN_H    0.001f
#define MIN_D    0.001f

#define MTS      64
#define NTHREADS 512

#define PADH     520
#define PADW     520
#define PADW2    264

// g_img per-flow-block layout (bytes):
//  L0: 2 chunks x 33280   (chunk = 16 k-rows: hi 16640 + lo 16640)
//  L1: 32 chunks x 33280
//  L2: 16 chunks x 33792  (chunk = 32 k-rows: hi 16896 + lo 16896)
#define L0_OFF   0
#define L1_OFF   66560
#define L2_OFF   1131520
#define BLK_BYTES 1672192

// smem byte offsets
#define OFF_AH   0         // activation [64 x 520] fp16 = 66560 (also fp32 park 64x260)
#define OFF_W    66560     // 2 weight slots x 67584
#define WSLOT    67584
#define OFF_IH   201728    // input tile hi [64 x 40] fp16
#define OFF_IL   206848    // input tile lo
#define SMEM_TOTAL 211968

__device__ float g_z[NS * DIMS];
__device__ __align__(16) uint8_t g_img[(size_t)NBLOCKS * BLK_BYTES];

__device__ __forceinline__ uint32_t smem_u32(const void* p) {
    return (uint32_t)__cvta_generic_to_shared(p);
}
#define CP16(s, g)  asm volatile("cp.async.cg.shared.global [%0], [%1], 16;" :: "r"(s), "l"(g))
#define CPCOMMIT()  asm volatile("cp.async.commit_group;")
#define CPWAIT0()   asm volatile("cp.async.wait_group 0;" ::: "memory")

__device__ __forceinline__ void ldm4(uint32_t* r, uint32_t a) {
    asm volatile("ldmatrix.sync.aligned.m8n8.x4.shared.b16 {%0,%1,%2,%3}, [%4];"
        : "=r"(r[0]), "=r"(r[1]), "=r"(r[2]), "=r"(r[3]) : "r"(a));
}
__device__ __forceinline__ void ldm4t(uint32_t* r, uint32_t a) {
    asm volatile("ldmatrix.sync.aligned.m8n8.x4.trans.shared.b16 {%0,%1,%2,%3}, [%4];"
        : "=r"(r[0]), "=r"(r[1]), "=r"(r[2]), "=r"(r[3]) : "r"(a));
}
__device__ __forceinline__ void mma16816(float* d, const uint32_t* a, uint32_t b0, uint32_t b1) {
    asm volatile("mma.sync.aligned.m16n8k16.row.col.f32.f16.f16.f32 "
        "{%0,%1,%2,%3}, {%4,%5,%6,%7}, {%8,%9}, {%0,%1,%2,%3};"
        : "+f"(d[0]), "+f"(d[1]), "+f"(d[2]), "+f"(d[3])
        : "r"(a[0]), "r"(a[1]), "r"(a[2]), "r"(a[3]), "r"(b0), "r"(b1));
}
__device__ __forceinline__ int insert_bit(int f, int p, int bit) {
    int lo = f & ((1 << p) - 1);
    int hi = f >> p;
    return (hi << (p + 1)) | (bit << p) | lo;
}

// ---------------- init ----------------
__global__ void init_kernel(const float* __restrict__ x, float* __restrict__ out) {
    int i = blockIdx.x * blockDim.x + threadIdx.x;
    if (i < NS * DIMS) g_z[i] = x[i];
    if (i < NS) out[i] = 0.f;
}

// ---------------- weight image prep ----------------
__global__ void prep_kernel(const float* __restrict__ W0,
                            const float* __restrict__ W1,
                            const float* __restrict__ W2) {
    int plane = blockIdx.x;
    int b = plane / 100, r = plane % 100;
    uint8_t* gb = g_img + (size_t)b * BLK_BYTES;
    int layer, chunk, half;
    if (r < 4)       { layer = 0; chunk = r >> 1;        half = r & 1; }
    else if (r < 68) { int q = r - 4;  layer = 1; chunk = q >> 1; half = q & 1; }
    else             { int q = r - 68; layer = 2; chunk = q >> 1; half = q & 1; }

    int rows  = (layer == 2) ? 32 : 16;
    int padc  = (layer == 2) ? PADW2 : PADW;
    int ncols = (layer == 2) ? FEAT_OUT : UNITS;
    uint8_t* dst;
    if (layer == 0)      dst = gb + L0_OFF + chunk * 33280 + half * 16640;
    else if (layer == 1) dst = gb + L1_OFF + chunk * 33280 + half * 16640;
    else                 dst = gb + L2_OFF + chunk * 33792 + half * 16896;
    __half* d16 = (__half*)dst;

    for (int i = threadIdx.x; i < rows * padc; i += blockDim.x) {
        int row = i / padc, col = i % padc;
        int k = chunk * rows + row;
        float w = 0.f;
        if (col < ncols) {
            if (layer == 0)      { if (k < FEAT_IN) w = W0[((size_t)b * FEAT_IN + k) * UNITS + col]; }
            else if (layer == 1) { w = W1[((size_t)b * UNITS + k) * UNITS + col]; }
            else                 { w = W2[((size_t)b * UNITS + k) * FEAT_OUT + col]; }
        }
        __half hi = __float2half(w);
        float v = half ? (w - __half2float(hi)) : w;
        d16[i] = __float2half(v);
    }
}

// ---------------- helpers ----------------
__device__ __forceinline__ void copy16(uint32_t sdst, const uint8_t* g, int n16, int tid) {
    for (int i = tid; i < n16; i += NTHREADS)
        CP16(sdst + i * 16, g + (size_t)i * 16);
}

// epilogue L0/L1: bias+relu -> fp16 activation tile.  warp = m64 x n32
// acc layout: acc[mh*16 + np*8 + j*4 + rr*2 + e]
__device__ __forceinline__ void epi_h(float* acc, const float* __restrict__ bias,
                                      uint8_t* sm, int nw, int lane) {
    int rq = lane >> 2;
    int c0 = (lane & 3) * 2;
    uint8_t* AH = sm + OFF_AH;
    #pragma unroll
    for (int np = 0; np < 2; np++) {
        #pragma unroll
        for (int j = 0; j < 2; j++) {
            int col = nw * 32 + np * 16 + j * 8 + c0;
            float bx = bias[col], by = bias[col + 1];
            #pragma unroll
            for (int mh = 0; mh < 4; mh++) {
                float* a = acc + mh * 16 + np * 8 + j * 4;
                #pragma unroll
                for (int rr = 0; rr < 2; rr++) {
                    float vx = fmaxf(a[rr * 2 + 0] + bx, 0.f);
                    float vy = fmaxf(a[rr * 2 + 1] + by, 0.f);
                    int row = mh * 16 + rr * 8 + rq;
                    uint32_t off = (uint32_t)(row * PADH + col) * 2;
                    *(__half2*)(AH + off) = __halves2half2(__float2half(vx), __float2half(vy));
                }
            }
        }
    }
}

// ---------------- main fused flow-block kernel ----------------
__global__ void __launch_bounds__(NTHREADS, 1)
flow_block_kernel(int blk,
                  const float* __restrict__ cc,
                  const float* __restrict__ B0, const float* __restrict__ B1,
                  const float* __restrict__ B2,
                  float* __restrict__ out)
{
    extern __shared__ __align__(128) uint8_t sm[];
    const uint32_t s0 = smem_u32(sm);
    const int tid  = threadIdx.x;
    const int wid  = tid >> 5;
    const int lane = tid & 31;
    const int nw   = wid;          // L0/L1: 16 column groups x n32
    const int mw2  = wid & 1;      // L2: 2 sample groups x m32
    const int nw2  = wid >> 1;     // L2: 8 column groups x n32
    const int row0 = blockIdx.x * MTS;
    const int p    = blk >> 1;
    const int cbit = 1 - (blk & 1);
    const uint8_t* gb = g_img + (size_t)blk * BLK_BYTES;

    const int l15  = lane & 15;
    const int lhi  = lane >> 4;
    uint32_t aoffM[4], ioffM[4];
    #pragma unroll
    for (int mh = 0; mh < 4; mh++) {
        aoffM[mh] = (uint32_t)((mh * 16 + l15) * (PADH * 2)) + lhi * 16;
        ioffM[mh] = (uint32_t)((mh * 16 + l15) * 80) + lhi * 16;
    }
    const int ar2  = mw2 * 32 + l15;
    const uint32_t aoff2_0 = (uint32_t)(ar2 * (PADH * 2)) + lhi * 16;
    const uint32_t aoff2_1 = aoff2_0 + 16 * (PADH * 2);

    const int krow = (lane & 7) + ((lane >> 3) & 1) * 8;
    const uint32_t woff1 = (uint32_t)(krow * (PADW * 2))  + (uint32_t)lhi * 16;
    const uint32_t woff2 = (uint32_t)(krow * (PADW2 * 2)) + (uint32_t)lhi * 16;

    // ---- stage L0 weights (66560 B) ----
    copy16(s0 + OFF_W, gb + L0_OFF, 4160, tid);
    CPCOMMIT();

    // ---- build input tile [64 x 32] fp16 hi/lo, zero-padded ----
    for (int i = tid; i < 1280; i += NTHREADS) {
        ((uint32_t*)(sm + OFF_IH))[i] = 0u;
        ((uint32_t*)(sm + OFF_IL))[i] = 0u;
    }
    __syncthreads();
    for (int i = tid; i < MTS * FEAT_IN; i += NTHREADS) {
        int m = i / FEAT_IN, f = i % FEAT_IN;
        float v = (f < DT) ? g_z[(row0 + m) * DIMS + insert_bit(f, p, cbit)]
                           : cc[(row0 + m) * DIMSC + (f - DT)];
        __half hi = __float2half(v);
        ((__half*)(sm + OFF_IH))[m * 40 + f] = hi;
        ((__half*)(sm + OFF_IL))[m * 40 + f] = __float2half(v - __half2float(hi));
    }
    CPWAIT0();
    __syncthreads();

    float acc[64];
    #pragma unroll
    for (int i = 0; i < 64; i++) acc[i] = 0.f;

    // ---- L0: 2 k16-steps, 3-pass (ah*bh, ah*bl, al*bh), warp = m64 x n32 ----
    #pragma unroll
    for (int ks = 0; ks < 2; ks++) {
        uint32_t ah[4][4], al[4][4];
        #pragma unroll
        for (int mh = 0; mh < 4; mh++) {
            ldm4(ah[mh], s0 + OFF_IH + ioffM[mh] + ks * 32);
            ldm4(al[mh], s0 + OFF_IL + ioffM[mh] + ks * 32);
        }
        uint32_t wb = s0 + OFF_W + ks * 33280;
        #pragma unroll
        for (int np = 0; np < 2; np++) {
            uint32_t bh[4], bl[4];
            uint32_t ba = wb + woff1 + (uint32_t)(nw * 32 + np * 16) * 2;
            ldm4t(bh, ba);
            ldm4t(bl, ba + 16640);
            #pragma unroll
            for (int mh = 0; mh < 4; mh++) {
                float* d0 = acc + mh * 16 + np * 8;
                mma16816(d0,     ah[mh], bh[0], bh[1]);
                mma16816(d0 + 4, ah[mh], bh[2], bh[3]);
            }
            #pragma unroll
            for (int mh = 0; mh < 4; mh++) {
                float* d0 = acc + mh * 16 + np * 8;
                mma16816(d0,     ah[mh], bl[0], bl[1]);
                mma16816(d0 + 4, ah[mh], bl[2], bl[3]);
            }
            #pragma unroll
            for (int mh = 0; mh < 4; mh++) {
                float* d0 = acc + mh * 16 + np * 8;
                mma16816(d0,     al[mh], bh[0], bh[1]);
                mma16816(d0 + 4, al[mh], bh[2], bh[3]);
            }
        }
    }
    __syncthreads();   // L0 weight reads retired

    // ---- L1 prologue: copy chunk 0, epilogue0 overlapped ----
    copy16(s0 + OFF_W, gb + L1_OFF, 4160, tid);
    CPCOMMIT();
    epi_h(acc, B0, sm, nw, lane);
    #pragma unroll
    for (int i = 0; i < 64; i++) acc[i] = 0.f;

    // ---- L1: 16 k32-chunks, single-sync pipeline, warp = m64 x n32 ----
    for (int c = 0; c < 16; c++) {
        CPWAIT0();          // chunk c arrived
        __syncthreads();    // visible to all; prior chunk's buffer reads retired
        if (c + 1 < 16) {
            copy16(s0 + OFF_W + ((c + 1) & 1) * WSLOT,
                   gb + L1_OFF + (size_t)(c + 1) * 66560, 4160, tid);
            CPCOMMIT();
        }
        uint32_t buf = s0 + OFF_W + (c & 1) * WSLOT;
        #pragma unroll
        for (int ks2 = 0; ks2 < 2; ks2++) {
            uint32_t ah[4][4];
            uint32_t ao = (uint32_t)(c * 64 + ks2 * 32);
            #pragma unroll
            for (int mh = 0; mh < 4; mh++)
                ldm4(ah[mh], s0 + OFF_AH + aoffM[mh] + ao);
            uint32_t wb = buf + ks2 * 33280;
            #pragma unroll
            for (int np = 0; np < 2; np++) {
                uint32_t bh[4], bl[4];
                uint32_t ba = wb + woff1 + (uint32_t)(nw * 32 + np * 16) * 2;
                ldm4t(bh, ba);
                ldm4t(bl, ba + 16640);
                #pragma unroll
                for (int mh = 0; mh < 4; mh++) {
                    float* d0 = acc + mh * 16 + np * 8;
                    mma16816(d0,     ah[mh], bh[0], bh[1]);
                    mma16816(d0 + 4, ah[mh], bh[2], bh[3]);
                }
                #pragma unroll
                for (int mh = 0; mh < 4; mh++) {
                    float* d0 = acc + mh * 16 + np * 8;
                    mma16816(d0,     ah[mh], bl[0], bl[1]);
                    mma16816(d0 + 4, ah[mh], bl[2], bl[3]);
                }
            }
        }
    }
    __syncthreads();   // L1 chunk 15 compute retired (act reads done)

    // ---- L2 prologue (k64 chunk 0) + epilogue1 ----
    copy16(s0 + OFF_W, gb + L2_OFF, 4224, tid);
    CPCOMMIT();
    epi_h(acc, B1, sm, nw, lane);

    float acc2[32];
    #pragma unroll
    for (int i = 0; i < 32; i++) acc2[i] = 0.f;

    // ---- L2: 8 k64-chunks, single-sync pipeline, warp = m32 x n32 ----
    for (int c = 0; c < 8; c++) {
        CPWAIT0();
        __syncthreads();
        if (c + 1 < 8) {
            copy16(s0 + OFF_W + ((c + 1) & 1) * WSLOT,
                   gb + L2_OFF + (size_t)(c + 1) * 67584, 4224, tid);
            CPCOMMIT();
        }
        uint32_t buf = s0 + OFF_W + (c & 1) * WSLOT;
        #pragma unroll
        for (int sub = 0; sub < 2; sub++) {
            uint32_t wbs = buf + sub * 33792;
            #pragma unroll
            for (int ks = 0; ks < 2; ks++) {
                uint32_t ah0[4], ah1[4];
                uint32_t ao = (uint32_t)(c * 128 + sub * 64 + ks * 32);
                ldm4(ah0, s0 + OFF_AH + aoff2_0 + ao);
                ldm4(ah1, s0 + OFF_AH + aoff2_1 + ao);
                #pragma unroll
                for (int np = 0; np < 2; np++) {
                    uint32_t bh[4], bl[4];
                    uint32_t ba = wbs + (uint32_t)(ks * 16 * PADW2 * 2) + woff2
                                + (uint32_t)(nw2 * 32 + np * 16) * 2;
                    ldm4t(bh, ba);
                    ldm4t(bl, ba + 16896);
                    float* d00 = acc2 + np * 16;
                    float* d01 = acc2 + np * 16 + 4;
                    float* d10 = acc2 + np * 16 + 8;
                    float* d11 = acc2 + np * 16 + 12;
                    mma16816(d00, ah0, bh[0], bh[1]);
                    mma16816(d10, ah1, bh[0], bh[1]);
                    mma16816(d01, ah0, bh[2], bh[3]);
                    mma16816(d11, ah1, bh[2], bh[3]);
                    mma16816(d00, ah0, bl[0], bl[1]);
                    mma16816(d10, ah1, bl[0], bl[1]);
                    mma16816(d01, ah0, bl[2], bl[3]);
                    mma16816(d11, ah1, bl[2], bl[3]);
                }
            }
        }
    }
    __syncthreads();   // L2 act reads retired

    // ---- park params fp32 into AH region (h dead) ----
    float* park = (float*)(sm + OFF_AH);
    {
        int rb = mw2 * 32 + (lane >> 2);
        int c0 = (lane & 3) * 2;
        #pragma unroll
        for (int np = 0; np < 2; np++) {
            #pragma unroll
            for (int j = 0; j < 2; j++) {
                int col = nw2 * 32 + np * 16 + j * 8 + c0;
                #pragma unroll
                for (int mh = 0; mh < 2; mh++) {
                    float* a = acc2 + np * 16 + mh * 8 + j * 4;
                    #pragma unroll
                    for (int rr = 0; rr < 2; rr++) {
                        int row = rb + mh * 16 + rr * 8;
                        *(float2*)(park + row * 260 + col) = make_float2(a[rr * 2 + 0], a[rr * 2 + 1]);
                    }
                }
            }
        }
    }
    __syncthreads();

    // ---- spline + logdet (fast-math intrinsics) ----
    {
        const int m2 = tid >> 3;
        const int dg = tid & 7;
        float pr[31];
        #pragma unroll
        for (int j = 0; j < 31; j++)
            pr[j] = park[m2 * 260 + dg * 31 + j] + B2[dg * 31 + j];

        const int tdim = insert_bit(dg, p, 1 - cbit);
        const float xv = g_z[(row0 + m2) * DIMS + tdim];

        float ww[BINS], hh[BINS], dd[BINS + 1];
        float mx = pr[0];
        #pragma unroll
        for (int i = 1; i < BINS; i++) mx = fmaxf(mx, pr[i]);
        float ssum = 0.f;
        #pragma unroll
        for (int i = 0; i < BINS; i++) { ww[i] = __expf(pr[i] - mx); ssum += ww[i]; }
        float sc = (1.0f - MIN_W * (float)BINS) / ssum;
        #pragma unroll
        for (int i = 0; i < BINS; i++) ww[i] = MIN_W + ww[i] * sc;

        mx = pr[BINS];
        #pragma unroll
        for (int i = 1; i < BINS; i++) mx = fmaxf(mx, pr[BINS + i]);
        ssum = 0.f;
        #pragma unroll
        for (int i = 0; i < BINS; i++) { hh[i] = __expf(pr[BINS + i] - mx); ssum += hh[i]; }
        sc = (1.0f - MIN_H * (float)BINS) / ssum;
        #pragma unroll
        for (int i = 0; i < BINS; i++) hh[i] = MIN_H + hh[i] * sc;

        #pragma unroll
        for (int i = 0; i <= BINS; i++) {
            float u = pr[2 * BINS + i];
            dd[i] = MIN_D + (fmaxf(u, 0.f) + log1pf(__expf(-fabsf(u))));
        }

        float cw[BINS + 1], ch[BINS + 1];
        cw[0] = 0.f; ch[0] = 0.f;
        #pragma unroll
        for (int i = 1; i <= BINS; i++) { cw[i] = cw[i-1] + ww[i-1]; ch[i] = ch[i-1] + hh[i-1]; }

        int cnt = 0;
        #pragma unroll
        for (int i = 0; i <= BINS; i++) cnt += (xv >= cw[i]) ? 1 : 0;
        int idx = cnt - 1;
        idx = idx < 0 ? 0 : (idx > BINS - 1 ? BINS - 1 : idx);

        float xk = 0.f, wk = 1.f, yk = 0.f, hk = 1.f, dk = 1.f, dk1 = 1.f;
        #pragma unroll
        for (int i = 0; i < BINS; i++)
            if (i == idx) { xk = cw[i]; wk = ww[i]; yk = ch[i]; hk = hh[i]; dk = dd[i]; dk1 = dd[i+1]; }

        float th  = fminf(fmaxf((xv - xk) / wk, 0.f), 1.f);
        float sr  = hk / wk;
        float t1  = th * (1.f - th);
        float den = sr + (dk1 + dk - 2.f * sr) * t1;
        float y   = yk + hk * (sr * th * th + dk * t1) / den;
        float omt = 1.f - th;
        float ld  = 2.f * __logf(sr)
                  + __logf(dk1 * th * th + 2.f * sr * t1 + dk * omt * omt)
                  - 2.f * __logf(den);

        g_z[(row0 + m2) * DIMS + tdim] = y;

        #pragma unroll
        for (int off = 4; off > 0; off >>= 1)
            ld += __shfl_down_sync(0xffffffffu, ld, off);
        if (dg == 0) out[row0 + m2] += ld;
    }
}

extern "C" void kernel_launch(void* const* d_in, const int* in_sizes, int n_in,
                              void* d_out, int out_size) {
    const float* x  = (const float*)d_in[0];
    const float* c  = (const float*)d_in[1];
    const float* W0 = (const float*)d_in[2];
    const float* b0 = (const float*)d_in[3];
    const float* W1 = (const float*)d_in[4];
    const float* b1 = (const float*)d_in[5];
    const float* W2 = (const float*)d_in[6];
    const float* b2 = (const float*)d_in[7];
    float* out = (float*)d_out;

    cudaFuncSetAttribute(flow_block_kernel,
                         cudaFuncAttributeMaxDynamicSharedMemorySize, SMEM_TOTAL);

    init_kernel<<<(NS * DIMS + 255) / 256, 256>>>(x, out);
    prep_kernel<<<NBLOCKS * 100, 256>>>(W0, W1, W2);

    for (int b = 0; b < NBLOCKS; b++) {
        flow_block_kernel<<<NS / MTS, NTHREADS, SMEM_TOTAL>>>(
            b, c,
            b0 + (size_t)b * UNITS,
            b1 + (size_t)b * UNITS,
            b2 + (size_t)b * FEAT_OUT,
            out);
    }
}

// round 14
// speedup vs baseline: 1.1980x; 1.0415x over previous
#include <cuda_runtime.h>
#include <cuda_fp16.h>
#include <math.h>
#include <stdint.h>

#define NS       131072
#define DIMS     16
#define DIMSC    16
#define UNITS    512
#define BINS     10
#define DT       8
#define FEAT_IN  24
#define FEAT_OUT 248
#define NBLOCKS  8
#define MIN_W    0.001f
#define MIN_H    0.001f
#define MIN_D    0.001f

#define MTS      64
#define NTHREADS 512

#define PADH     520
#define PADW     520
#define PADW2    264

// g_img per-flow-block layout (bytes):
//  L0: 2 chunks x 33280   (chunk = 16 k-rows: hi 16640 + lo 16640)
//  L1: 32 chunks x 33280
//  L2: 16 chunks x 33792  (chunk = 32 k-rows: hi 16896 + lo 16896)
#define L0_OFF   0
#define L1_OFF   66560
#define L2_OFF   1131520
#define BLK_BYTES 1672192

// smem byte offsets
#define OFF_AH   0         // activation [64 x 520] fp16 = 66560 (also fp32 park 64x260)
#define OFF_W    66560     // 2 weight slots x 67584
#define WSLOT    67584
#define OFF_IH   201728    // input tile hi [64 x 40] fp16
#define OFF_IL   206848    // input tile lo
#define OFF_Z    211968    // z state [64 x 16] fp32 = 4096
#define OFF_C    216064    // cond   [64 x 16] fp32 = 4096
#define SMEM_TOTAL 220160

__device__ __align__(16) uint8_t g_img[(size_t)NBLOCKS * BLK_BYTES];

__device__ __forceinline__ uint32_t smem_u32(const void* p) {
    return (uint32_t)__cvta_generic_to_shared(p);
}
#define CP16(s, g)  asm volatile("cp.async.cg.shared.global [%0], [%1], 16;" :: "r"(s), "l"(g))
#define CPCOMMIT()  asm volatile("cp.async.commit_group;")
#define CPWAIT0()   asm volatile("cp.async.wait_group 0;" ::: "memory")

__device__ __forceinline__ void ldm4(uint32_t* r, uint32_t a) {
    asm volatile("ldmatrix.sync.aligned.m8n8.x4.shared.b16 {%0,%1,%2,%3}, [%4];"
        : "=r"(r[0]), "=r"(r[1]), "=r"(r[2]), "=r"(r[3]) : "r"(a));
}
__device__ __forceinline__ void ldm4t(uint32_t* r, uint32_t a) {
    asm volatile("ldmatrix.sync.aligned.m8n8.x4.trans.shared.b16 {%0,%1,%2,%3}, [%4];"
        : "=r"(r[0]), "=r"(r[1]), "=r"(r[2]), "=r"(r[3]) : "r"(a));
}
__device__ __forceinline__ void mma16816(float* d, const uint32_t* a, uint32_t b0, uint32_t b1) {
    asm volatile("mma.sync.aligned.m16n8k16.row.col.f32.f16.f16.f32 "
        "{%0,%1,%2,%3}, {%4,%5,%6,%7}, {%8,%9}, {%0,%1,%2,%3};"
        : "+f"(d[0]), "+f"(d[1]), "+f"(d[2]), "+f"(d[3])
        : "r"(a[0]), "r"(a[1]), "r"(a[2]), "r"(a[3]), "r"(b0), "r"(b1));
}
__device__ __forceinline__ int insert_bit(int f, int p, int bit) {
    int lo = f & ((1 << p) - 1);
    int hi = f >> p;
    return (hi << (p + 1)) | (bit << p) | lo;
}

// ---------------- weight image prep (unchanged layout) ----------------
__global__ void prep_kernel(const float* __restrict__ W0,
                            const float* __restrict__ W1,
                            const float* __restrict__ W2) {
    int plane = blockIdx.x;
    int b = plane / 100, r = plane % 100;
    uint8_t* gb = g_img + (size_t)b * BLK_BYTES;
    int layer, chunk, half;
    if (r < 4)       { layer = 0; chunk = r >> 1;        half = r & 1; }
    else if (r < 68) { int q = r - 4;  layer = 1; chunk = q >> 1; half = q & 1; }
    else             { int q = r - 68; layer = 2; chunk = q >> 1; half = q & 1; }

    int rows  = (layer == 2) ? 32 : 16;
    int padc  = (layer == 2) ? PADW2 : PADW;
    int ncols = (layer == 2) ? FEAT_OUT : UNITS;
    uint8_t* dst;
    if (layer == 0)      dst = gb + L0_OFF + chunk * 33280 + half * 16640;
    else if (layer == 1) dst = gb + L1_OFF + chunk * 33280 + half * 16640;
    else                 dst = gb + L2_OFF + chunk * 33792 + half * 16896;
    __half* d16 = (__half*)dst;

    for (int i = threadIdx.x; i < rows * padc; i += blockDim.x) {
        int row = i / padc, col = i % padc;
        int k = chunk * rows + row;
        float w = 0.f;
        if (col < ncols) {
            if (layer == 0)      { if (k < FEAT_IN) w = W0[((size_t)b * FEAT_IN + k) * UNITS + col]; }
            else if (layer == 1) { w = W1[((size_t)b * UNITS + k) * UNITS + col]; }
            else                 { w = W2[((size_t)b * UNITS + k) * FEAT_OUT + col]; }
        }
        __half hi = __float2half(w);
        float v = half ? (w - __half2float(hi)) : w;
        d16[i] = __float2half(v);
    }
}

// ---------------- helpers ----------------
__device__ __forceinline__ void copy16(uint32_t sdst, const uint8_t* g, int n16, int tid) {
    for (int i = tid; i < n16; i += NTHREADS)
        CP16(sdst + i * 16, g + (size_t)i * 16);
}

// epilogue L0/L1: bias+relu -> fp16 activation tile.  warp = m64 x n32
__device__ __forceinline__ void epi_h(float* acc, const float* __restrict__ bias,
                                      uint8_t* sm, int nw, int lane) {
    int rq = lane >> 2;
    int c0 = (lane & 3) * 2;
    uint8_t* AH = sm + OFF_AH;
    #pragma unroll
    for (int np = 0; np < 2; np++) {
        #pragma unroll
        for (int j = 0; j < 2; j++) {
            int col = nw * 32 + np * 16 + j * 8 + c0;
            float bx = bias[col], by = bias[col + 1];
            #pragma unroll
            for (int mh = 0; mh < 4; mh++) {
                float* a = acc + mh * 16 + np * 8 + j * 4;
                #pragma unroll
                for (int rr = 0; rr < 2; rr++) {
                    float vx = fmaxf(a[rr * 2 + 0] + bx, 0.f);
                    float vy = fmaxf(a[rr * 2 + 1] + by, 0.f);
                    int row = mh * 16 + rr * 8 + rq;
                    uint32_t off = (uint32_t)(row * PADH + col) * 2;
                    *(__half2*)(AH + off) = __halves2half2(__float2half(vx), __float2half(vy));
                }
            }
        }
    }
}

// ---------------- fused 8-block megakernel ----------------
__global__ void __launch_bounds__(NTHREADS, 1)
flow_mega_kernel(const float* __restrict__ x,
                 const float* __restrict__ cc,
                 const float* __restrict__ b0a, const float* __restrict__ b1a,
                 const float* __restrict__ b2a,
                 float* __restrict__ out)
{
    extern __shared__ __align__(128) uint8_t sm[];
    const uint32_t s0 = smem_u32(sm);
    const int tid  = threadIdx.x;
    const int wid  = tid >> 5;
    const int lane = tid & 31;
    const int nw   = wid;          // L0/L1: 16 column groups x n32
    const int mw2  = wid & 1;      // L2: 2 sample groups x m32
    const int nw2  = wid >> 1;     // L2: 8 column groups x n32
    const int row0 = blockIdx.x * MTS;

    const int l15  = lane & 15;
    const int lhi  = lane >> 4;
    uint32_t aoffM[4], ioffM[4];
    #pragma unroll
    for (int mh = 0; mh < 4; mh++) {
        aoffM[mh] = (uint32_t)((mh * 16 + l15) * (PADH * 2)) + lhi * 16;
        ioffM[mh] = (uint32_t)((mh * 16 + l15) * 80) + lhi * 16;
    }
    const int ar2  = mw2 * 32 + l15;
    const uint32_t aoff2_0 = (uint32_t)(ar2 * (PADH * 2)) + lhi * 16;
    const uint32_t aoff2_1 = aoff2_0 + 16 * (PADH * 2);

    const int krow = (lane & 7) + ((lane >> 3) & 1) * 8;
    const uint32_t woff1 = (uint32_t)(krow * (PADW * 2))  + (uint32_t)lhi * 16;
    const uint32_t woff2 = (uint32_t)(krow * (PADW2 * 2)) + (uint32_t)lhi * 16;

    float* s_z = (float*)(sm + OFF_Z);
    float* s_c = (float*)(sm + OFF_C);

    // ---- one-time: stage block0 L0 weights + load z (from x) and c into smem ----
    copy16(s0 + OFF_W, g_img + L0_OFF, 4160, tid);
    CPCOMMIT();
    for (int i = tid; i < MTS * DIMS / 4; i += NTHREADS) {
        ((float4*)s_z)[i] = ((const float4*)(x  + (size_t)row0 * DIMS))[i];
        ((float4*)s_c)[i] = ((const float4*)(cc + (size_t)row0 * DIMSC))[i];
    }
    __syncthreads();

    float ld_acc = 0.f;

    for (int blk = 0; blk < NBLOCKS; blk++) {
        const int p    = blk >> 1;
        const int cbit = 1 - (blk & 1);
        const uint8_t* gb = g_img + (size_t)blk * BLK_BYTES;
        const float* B0 = b0a + (size_t)blk * UNITS;
        const float* B1 = b1a + (size_t)blk * UNITS;
        const float* B2 = b2a + (size_t)blk * FEAT_OUT;

        // ---- build input tile [64 x 32] fp16 hi/lo, zero-padded ----
        for (int i = tid; i < 1280; i += NTHREADS) {
            ((uint32_t*)(sm + OFF_IH))[i] = 0u;
            ((uint32_t*)(sm + OFF_IL))[i] = 0u;
        }
        __syncthreads();
        for (int i = tid; i < MTS * FEAT_IN; i += NTHREADS) {
            int m = i / FEAT_IN, f = i % FEAT_IN;
            float v = (f < DT) ? s_z[m * DIMS + insert_bit(f, p, cbit)]
                               : s_c[m * DIMSC + (f - DT)];
            __half hi = __float2half(v);
            ((__half*)(sm + OFF_IH))[m * 40 + f] = hi;
            ((__half*)(sm + OFF_IL))[m * 40 + f] = __float2half(v - __half2float(hi));
        }
        CPWAIT0();
        __syncthreads();

        float acc[64];
        #pragma unroll
        for (int i = 0; i < 64; i++) acc[i] = 0.f;

        // ---- L0: 2 k16-steps, 3-pass, warp = m64 x n32 ----
        #pragma unroll
        for (int ks = 0; ks < 2; ks++) {
            uint32_t ah[4][4], al[4][4];
            #pragma unroll
            for (int mh = 0; mh < 4; mh++) {
                ldm4(ah[mh], s0 + OFF_IH + ioffM[mh] + ks * 32);
                ldm4(al[mh], s0 + OFF_IL + ioffM[mh] + ks * 32);
            }
            uint32_t wb = s0 + OFF_W + ks * 33280;
            #pragma unroll
            for (int np = 0; np < 2; np++) {
                uint32_t bh[4], bl[4];
                uint32_t ba = wb + woff1 + (uint32_t)(nw * 32 + np * 16) * 2;
                ldm4t(bh, ba);
                ldm4t(bl, ba + 16640);
                #pragma unroll
                for (int mh = 0; mh < 4; mh++) {
                    float* d0 = acc + mh * 16 + np * 8;
                    mma16816(d0,     ah[mh], bh[0], bh[1]);
                    mma16816(d0 + 4, ah[mh], bh[2], bh[3]);
                }
                #pragma unroll
                for (int mh = 0; mh < 4; mh++) {
                    float* d0 = acc + mh * 16 + np * 8;
                    mma16816(d0,     ah[mh], bl[0], bl[1]);
                    mma16816(d0 + 4, ah[mh], bl[2], bl[3]);
                }
                #pragma unroll
                for (int mh = 0; mh < 4; mh++) {
                    float* d0 = acc + mh * 16 + np * 8;
                    mma16816(d0,     al[mh], bh[0], bh[1]);
                    mma16816(d0 + 4, al[mh], bh[2], bh[3]);
                }
            }
        }
        __syncthreads();   // L0 weight reads retired

        // ---- L1 prologue: copy chunk 0, epilogue0 overlapped ----
        copy16(s0 + OFF_W, gb + L1_OFF, 4160, tid);
        CPCOMMIT();
        epi_h(acc, B0, sm, nw, lane);
        #pragma unroll
        for (int i = 0; i < 64; i++) acc[i] = 0.f;

        // ---- L1: 16 k32-chunks, single-sync pipeline, warp = m64 x n32 ----
        for (int c = 0; c < 16; c++) {
            CPWAIT0();
            __syncthreads();
            if (c + 1 < 16) {
                copy16(s0 + OFF_W + ((c + 1) & 1) * WSLOT,
                       gb + L1_OFF + (size_t)(c + 1) * 66560, 4160, tid);
                CPCOMMIT();
            }
            uint32_t buf = s0 + OFF_W + (c & 1) * WSLOT;
            #pragma unroll
            for (int ks2 = 0; ks2 < 2; ks2++) {
                uint32_t ah[4][4];
                uint32_t ao = (uint32_t)(c * 64 + ks2 * 32);
                #pragma unroll
                for (int mh = 0; mh < 4; mh++)
                    ldm4(ah[mh], s0 + OFF_AH + aoffM[mh] + ao);
                uint32_t wb = buf + ks2 * 33280;
                #pragma unroll
                for (int np = 0; np < 2; np++) {
                    uint32_t bh[4], bl[4];
                    uint32_t ba = wb + woff1 + (uint32_t)(nw * 32 + np * 16) * 2;
                    ldm4t(bh, ba);
                    ldm4t(bl, ba + 16640);
                    #pragma unroll
                    for (int mh = 0; mh < 4; mh++) {
                        float* d0 = acc + mh * 16 + np * 8;
                        mma16816(d0,     ah[mh], bh[0], bh[1]);
                        mma16816(d0 + 4, ah[mh], bh[2], bh[3]);
                    }
                    #pragma unroll
                    for (int mh = 0; mh < 4; mh++) {
                        float* d0 = acc + mh * 16 + np * 8;
                        mma16816(d0,     ah[mh], bl[0], bl[1]);
                        mma16816(d0 + 4, ah[mh], bl[2], bl[3]);
                    }
                }
            }
        }
        __syncthreads();   // L1 compute retired

        // ---- L2 prologue (k64 chunk 0) + epilogue1 ----
        copy16(s0 + OFF_W, gb + L2_OFF, 4224, tid);
        CPCOMMIT();
        epi_h(acc, B1, sm, nw, lane);

        float acc2[32];
        #pragma unroll
        for (int i = 0; i < 32; i++) acc2[i] = 0.f;

        // ---- L2: 8 k64-chunks, single-sync pipeline, warp = m32 x n32 ----
        for (int c = 0; c < 8; c++) {
            CPWAIT0();
            __syncthreads();
            if (c + 1 < 8) {
                copy16(s0 + OFF_W + ((c + 1) & 1) * WSLOT,
                       gb + L2_OFF + (size_t)(c + 1) * 67584, 4224, tid);
                CPCOMMIT();
            }
            uint32_t buf = s0 + OFF_W + (c & 1) * WSLOT;
            #pragma unroll
            for (int sub = 0; sub < 2; sub++) {
                uint32_t wbs = buf + sub * 33792;
                #pragma unroll
                for (int ks = 0; ks < 2; ks++) {
                    uint32_t ah0[4], ah1[4];
                    uint32_t ao = (uint32_t)(c * 128 + sub * 64 + ks * 32);
                    ldm4(ah0, s0 + OFF_AH + aoff2_0 + ao);
                    ldm4(ah1, s0 + OFF_AH + aoff2_1 + ao);
                    #pragma unroll
                    for (int np = 0; np < 2; np++) {
                        uint32_t bh[4], bl[4];
                        uint32_t ba = wbs + (uint32_t)(ks * 16 * PADW2 * 2) + woff2
                                    + (uint32_t)(nw2 * 32 + np * 16) * 2;
                        ldm4t(bh, ba);
                        ldm4t(bl, ba + 16896);
                        float* d00 = acc2 + np * 16;
                        float* d01 = acc2 + np * 16 + 4;
                        float* d10 = acc2 + np * 16 + 8;
                        float* d11 = acc2 + np * 16 + 12;
                        mma16816(d00, ah0, bh[0], bh[1]);
                        mma16816(d10, ah1, bh[0], bh[1]);
                        mma16816(d01, ah0, bh[2], bh[3]);
                        mma16816(d11, ah1, bh[2], bh[3]);
                        mma16816(d00, ah0, bl[0], bl[1]);
                        mma16816(d10, ah1, bl[0], bl[1]);
                        mma16816(d01, ah0, bl[2], bl[3]);
                        mma16816(d11, ah1, bl[2], bl[3]);
                    }
                }
            }
        }
        __syncthreads();   // L2 slot reads retired

        // ---- prefetch next block's L0 weights (overlaps park + spline) ----
        if (blk + 1 < NBLOCKS) {
            copy16(s0 + OFF_W, g_img + (size_t)(blk + 1) * BLK_BYTES + L0_OFF, 4160, tid);
            CPCOMMIT();
        }

        // ---- park params fp32 into AH region (h dead) ----
        float* park = (float*)(sm + OFF_AH);
        {
            int rb = mw2 * 32 + (lane >> 2);
            int c0 = (lane & 3) * 2;
            #pragma unroll
            for (int np = 0; np < 2; np++) {
                #pragma unroll
                for (int j = 0; j < 2; j++) {
                    int col = nw2 * 32 + np * 16 + j * 8 + c0;
                    #pragma unroll
                    for (int mh = 0; mh < 2; mh++) {
                        float* a = acc2 + np * 16 + mh * 8 + j * 4;
                        #pragma unroll
                        for (int rr = 0; rr < 2; rr++) {
                            int row = rb + mh * 16 + rr * 8;
                            *(float2*)(park + row * 260 + col) = make_float2(a[rr * 2 + 0], a[rr * 2 + 1]);
                        }
                    }
                }
            }
        }
        __syncthreads();

        // ---- spline + logdet (z and logdet stay on-chip) ----
        {
            const int m2 = tid >> 3;
            const int dg = tid & 7;
            float pr[31];
            #pragma unroll
            for (int j = 0; j < 31; j++)
                pr[j] = park[m2 * 260 + dg * 31 + j] + B2[dg * 31 + j];

            const int tdim = insert_bit(dg, p, 1 - cbit);
            const float xv = s_z[m2 * DIMS + tdim];

            float ww[BINS], hh[BINS], dd[BINS + 1];
            float mx = pr[0];
            #pragma unroll
            for (int i = 1; i < BINS; i++) mx = fmaxf(mx, pr[i]);
            float ssum = 0.f;
            #pragma unroll
            for (int i = 0; i < BINS; i++) { ww[i] = __expf(pr[i] - mx); ssum += ww[i]; }
            float sc = (1.0f - MIN_W * (float)BINS) / ssum;
            #pragma unroll
            for (int i = 0; i < BINS; i++) ww[i] = MIN_W + ww[i] * sc;

            mx = pr[BINS];
            #pragma unroll
            for (int i = 1; i < BINS; i++) mx = fmaxf(mx, pr[BINS + i]);
            ssum = 0.f;
            #pragma unroll
            for (int i = 0; i < BINS; i++) { hh[i] = __expf(pr[BINS + i] - mx); ssum += hh[i]; }
            sc = (1.0f - MIN_H * (float)BINS) / ssum;
            #pragma unroll
            for (int i = 0; i < BINS; i++) hh[i] = MIN_H + hh[i] * sc;

            #pragma unroll
            for (int i = 0; i <= BINS; i++) {
                float u = pr[2 * BINS + i];
                dd[i] = MIN_D + (fmaxf(u, 0.f) + log1pf(__expf(-fabsf(u))));
            }

            float cw[BINS + 1], ch[BINS + 1];
            cw[0] = 0.f; ch[0] = 0.f;
            #pragma unroll
            for (int i = 1; i <= BINS; i++) { cw[i] = cw[i-1] + ww[i-1]; ch[i] = ch[i-1] + hh[i-1]; }

            int cnt = 0;
            #pragma unroll
            for (int i = 0; i <= BINS; i++) cnt += (xv >= cw[i]) ? 1 : 0;
            int idx = cnt - 1;
            idx = idx < 0 ? 0 : (idx > BINS - 1 ? BINS - 1 : idx);

            float xk = 0.f, wk = 1.f, yk = 0.f, hk = 1.f, dk = 1.f, dk1 = 1.f;
            #pragma unroll
            for (int i = 0; i < BINS; i++)
                if (i == idx) { xk = cw[i]; wk = ww[i]; yk = ch[i]; hk = hh[i]; dk = dd[i]; dk1 = dd[i+1]; }

            float th  = fminf(fmaxf((xv - xk) / wk, 0.f), 1.f);
            float sr  = hk / wk;
            float t1  = th * (1.f - th);
            float den = sr + (dk1 + dk - 2.f * sr) * t1;
            float y   = yk + hk * (sr * th * th + dk * t1) / den;
            float omt = 1.f - th;
            float ld  = 2.f * __logf(sr)
                      + __logf(dk1 * th * th + 2.f * sr * t1 + dk * omt * omt)
                      - 2.f * __logf(den);

            s_z[m2 * DIMS + tdim] = y;

            #pragma unroll
            for (int off = 4; off > 0; off >>= 1)
                ld += __shfl_down_sync(0xffffffffu, ld, off);
            if (dg == 0) ld_acc += ld;
        }
        __syncthreads();   // z updated before next block's input build
    }

    // ---- final output ----
    {
        const int m2 = tid >> 3;
        const int dg = tid & 7;
        if (dg == 0) out[row0 + m2] = ld_acc;
    }
}

extern "C" void kernel_launch(void* const* d_in, const int* in_sizes, int n_in,
                              void* d_out, int out_size) {
    const float* x  = (const float*)d_in[0];
    const float* c  = (const float*)d_in[1];
    const float* W0 = (const float*)d_in[2];
    const float* b0 = (const float*)d_in[3];
    const float* W1 = (const float*)d_in[4];
    const float* b1 = (const float*)d_in[5];
    const float* W2 = (const float*)d_in[6];
    const float* b2 = (const float*)d_in[7];
    float* out = (float*)d_out;

    cudaFuncSetAttribute(flow_mega_kernel,
                         cudaFuncAttributeMaxDynamicSharedMemorySize, SMEM_TOTAL);

    prep_kernel<<<NBLOCKS * 100, 256>>>(W0, W1, W2);
    flow_mega_kernel<<<NS / MTS, NTHREADS, SMEM_TOTAL>>>(x, c, b0, b1, b2, out);
}